// round 15
// baseline (speedup 1.0000x reference)
#include <cuda_runtime.h>
#include <cuda_bf16.h>
#include <math.h>
#include <cstdint>

#define NROWS 8192
#define DDIM  64
#define MARGIN 1.1f
#define EPS 1e-8f
#define THREADS 128               // 4 warps per CTA
#define NWORKERS 592              // 4 CTAs/SM x 148 SMs, all wave-1 resident
#define NPREP 128                 // prep blocks (64 rows each)
#define NHT 4160                  // 2080 triangular 128-tiles x 2 halves
#define NUNITS 1792               // 592x4 + 592x2 + 608x1 = 4160
#define ROWB 144                  // padded smem row stride (bytes)
#define ABUF (64 * ROWB)          // 9216  (64-row A half-band)
#define BBUF (128 * ROWB)         // 18432 (128-row B band)
#define SMEM_TOTAL (2 * ABUF + 2 * BBUF + 64)   // 55360 B -> 4 CTAs/SM

// Scratch (no allocs allowed).
__device__ __align__(16) __nv_bfloat16 g_xb[NROWS * DDIM];
__device__ double   g_accum;          // zero-init; last block resets
__device__ unsigned g_prep_done;      // idem
__device__ unsigned g_done_ctr;       // idem
__device__ unsigned g_work;           // work cursor (reset each run)

__device__ __forceinline__ uint32_t smem_u32(const void* p) {
    uint32_t a;
    asm("{ .reg .u64 t; cvta.to.shared.u64 t, %1; cvt.u32.u64 %0, t; }"
        : "=r"(a) : "l"(p));
    return a;
}

__device__ __forceinline__ void ldsm_x4(uint32_t& r0, uint32_t& r1,
                                        uint32_t& r2, uint32_t& r3,
                                        uint32_t addr) {
    asm volatile("ldmatrix.sync.aligned.m8n8.x4.shared.b16 {%0,%1,%2,%3}, [%4];"
                 : "=r"(r0), "=r"(r1), "=r"(r2), "=r"(r3) : "r"(addr));
}

__device__ __forceinline__ void mma_16816(float* c, const uint32_t* a,
                                          uint32_t b0, uint32_t b1) {
    asm volatile(
        "mma.sync.aligned.m16n8k16.row.col.f32.bf16.bf16.f32 "
        "{%0,%1,%2,%3}, {%4,%5,%6,%7}, {%8,%9}, {%0,%1,%2,%3};"
        : "+f"(c[0]), "+f"(c[1]), "+f"(c[2]), "+f"(c[3])
        : "r"(a[0]), "r"(a[1]), "r"(a[2]), "r"(a[3]), "r"(b0), "r"(b1));
}

__device__ __forceinline__ void cpa16(uint32_t dst, const void* src) {
    asm volatile("cp.async.cg.shared.global [%0], [%1], 16;"
                 :: "r"(dst), "l"(src) : "memory");
}
#define CPA_COMMIT() asm volatile("cp.async.commit_group;" ::: "memory")
#define CPA_WAIT0()  asm volatile("cp.async.wait_group 0;" ::: "memory")

// Stage a 64-row A half-band (512 uint4) with 128 threads.
__device__ __forceinline__ void stage_a(uint32_t dstb,
                                        const __nv_bfloat16* src, int tid) {
    const char* s = (const char*)src;
    #pragma unroll
    for (int r = 0; r < 4; r++) {
        int idx = tid + r * THREADS;
        int row = idx >> 3;
        int ch  = idx & 7;
        cpa16(dstb + row * ROWB + ch * 16, s + idx * 16);
    }
}
// Stage a 128-row B band (1024 uint4) with 128 threads.
__device__ __forceinline__ void stage_b(uint32_t dstb,
                                        const __nv_bfloat16* src, int tid) {
    const char* s = (const char*)src;
    #pragma unroll
    for (int r = 0; r < 8; r++) {
        int idx = tid + r * THREADS;
        int row = idx >> 3;
        int ch  = idx & 7;
        cpa16(dstb + row * ROWB + ch * 16, s + idx * 16);
    }
}

// Linear triangular 128-tile id -> (bi, bj), bi <= bj, 64 bands.
__device__ __forceinline__ void tile_decode(int t, int& bi, int& bj) {
    int b = (int)((129.0f - sqrtf(16641.0f - 8.0f * (float)t)) * 0.5f);
    while (b * (129 - b) / 2 > t) b--;
    while ((b + 1) * (128 - b) / 2 <= t) b++;
    bi = b;
    bj = b + (t - b * (129 - b) / 2);
}

// ---------------------------------------------------------------------------
// Persistent fused kernel, 4 CTAs/SM x 128 threads: each CTA computes 64x128
// HALF-tiles of the triangular Gram, guided schedule (4 -> 2 -> 1). Four
// independent barrier domains per SM de-phase the ldsm/HMMA/epilogue bursts
// so the pipes overlap instead of taking turns (the R6..R14 plateau).
// ---------------------------------------------------------------------------
__global__ __launch_bounds__(THREADS, 4) void fused_kernel(
    const float* __restrict__ x, const int* __restrict__ cls,
    float* __restrict__ out) {

    extern __shared__ __align__(16) char dsm[];
    float* red   = (float*)(dsm + 2 * ABUF + 2 * BBUF);
    int*   sunit = (int*)(red + 4);

    const int bid  = blockIdx.x;
    const int tid  = threadIdx.x;
    const int wid  = tid >> 5;
    const int lane = tid & 31;

    // ---------------- Phase 1: prep (normalize -> bf16), blocks 0..127 -----
    if (bid < NPREP) {
        int t    = bid * THREADS + tid;     // [0, 16384)
        int row  = t >> 1;
        int half = t & 1;
        const float4* xr = (const float4*)(x + (size_t)row * DDIM + half * 32);
        float4 v[8];
        #pragma unroll
        for (int i = 0; i < 8; i++) v[i] = xr[i];
        float s = 0.0f;
        #pragma unroll
        for (int i = 0; i < 8; i++)
            s += v[i].x * v[i].x + v[i].y * v[i].y +
                 v[i].z * v[i].z + v[i].w * v[i].w;
        s += __shfl_xor_sync(0xffffffffu, s, 1);
        float inv = 1.0f / fmaxf(sqrtf(s), EPS);
        __nv_bfloat16* dst = g_xb + (size_t)row * DDIM + half * 32;
        #pragma unroll
        for (int i = 0; i < 8; i++) {
            __nv_bfloat162 p0 = {__float2bfloat16(v[i].x * inv),
                                 __float2bfloat16(v[i].y * inv)};
            __nv_bfloat162 p1 = {__float2bfloat16(v[i].z * inv),
                                 __float2bfloat16(v[i].w * inv)};
            *(__nv_bfloat162*)(dst + i * 4)     = p0;
            *(__nv_bfloat162*)(dst + i * 4 + 2) = p1;
        }
        __syncthreads();
        if (tid == 0) { __threadfence(); atomicAdd(&g_prep_done, 1u); }
    }

    // ---------------- Device-wide wait for prep ----------------------------
    if (tid == 0) {
        unsigned v;
        do {
            asm volatile("ld.acquire.gpu.u32 %0, [%1];"
                         : "=r"(v) : "l"(&g_prep_done));
            if (v < (unsigned)NPREP) __nanosleep(64);
        } while (v < (unsigned)NPREP);
    }
    __syncthreads();

    const int wm = wid & 1;          // 2 row groups of 32 (64-row half-band)
    const int wn = wid >> 1;         // 2 col groups of 64 (128-col band)
    const uint32_t aBufu[2] = { smem_u32(dsm), smem_u32(dsm + ABUF) };
    const uint32_t bBufu[2] = { smem_u32(dsm + 2 * ABUF),
                                smem_u32(dsm + 2 * ABUF + BBUF) };
    const uint32_t a_lane_off =
        (uint32_t)((wm * 32 + (lane & 15)) * ROWB + ((lane >> 4) << 4));
    const uint32_t b_lane_off =
        (uint32_t)((wn * 64 + (lane & 7) + ((lane >> 4) << 3)) * ROWB +
                   (((lane >> 3) & 1) << 4));
    const float MC = MARGIN - 1.0f;
    const int quad = lane >> 2;
    const int tq   = lane & 3;

    int curHB = -1;       // half-band id resident in aBufu[aCur] (after wait)
    int aCur  = 0;
    int aFhb  = -1;       // half-band id in aF registers
    int wcnt  = 0;        // half-tiles processed (B buffer parity)
    uint32_t aF[4][2][4];
    int ci00 = 0, ci01 = 0, ci10 = 0, ci11 = 0;
    float lsum = 0.0f;

    // ==================== Persistent guided-stealing loop ===================
    for (;;) {
        if (tid == 0) *sunit = (int)atomicAdd(&g_work, 1u);
        __syncthreads();
        const int u = *sunit;
        if (u >= NUNITS) break;

        int s, n;
        if (u < 592)       { s = u * 4;                n = 4; }
        else if (u < 1184) { s = 2368 + (u - 592) * 2; n = 2; }
        else               { s = 3552 + (u - 1184);    n = 1; }

        // first half-tile of the unit
        int cbi, cbj, ch;
        { int t128 = s >> 1; ch = s & 1; tile_decode(t128, cbi, cbj); }
        int chb = cbi * 2 + ch;
        if (chb != curHB)
            stage_a(aBufu[aCur ^ 1],
                    g_xb + (size_t)(cbi * 128 + ch * 64) * DDIM, tid);
        stage_b(bBufu[wcnt & 1], g_xb + (size_t)cbj * 128 * DDIM, tid);
        CPA_COMMIT();

        int nbi = cbi, nbj = cbj, nh = ch, nhb = chb;
        for (int i = 0; i < n; i++) {
            cbi = nbi; cbj = nbj; ch = nh; chb = nhb;
            CPA_WAIT0();
            __syncthreads();         // tile data ready; all warps past t-1
            if (chb != curHB) { aCur ^= 1; curHB = chb; }

            // prefetch next half-tile (A only if half-band changes)
            if (i + 1 < n) {
                int ht = s + i + 1;
                int t128 = ht >> 1; nh = ht & 1;
                tile_decode(t128, nbi, nbj);
                nhb = nbi * 2 + nh;
                if (nhb != curHB)
                    stage_a(aBufu[aCur ^ 1],
                            g_xb + (size_t)(nbi * 128 + nh * 64) * DDIM, tid);
                stage_b(bBufu[(wcnt + 1) & 1],
                        g_xb + (size_t)nbj * 128 * DDIM, tid);
                CPA_COMMIT();
            }

            // A fragments + row classes: refresh only on half-band change
            if (aFhb != chb) {
                const uint32_t ab = aBufu[aCur];
                #pragma unroll
                for (int k = 0; k < 4; k++)
                    #pragma unroll
                    for (int m = 0; m < 2; m++)
                        ldsm_x4(aF[k][m][0], aF[k][m][1],
                                aF[k][m][2], aF[k][m][3],
                                ab + a_lane_off + m * 16 * ROWB + k * 32);
                aFhb = chb;
                const int* cr = cls + cbi * 128 + ch * 64 + wm * 32 + quad;
                ci00 = __ldg(cr);     ci01 = __ldg(cr + 8);
                ci10 = __ldg(cr + 16); ci11 = __ldg(cr + 24);
            }

            const uint32_t b_base = bBufu[wcnt & 1];

            float c[2][8][4];
            #pragma unroll
            for (int m = 0; m < 2; m++)
                #pragma unroll
                for (int nn = 0; nn < 8; nn++)
                    #pragma unroll
                    for (int e = 0; e < 4; e++) c[m][nn][e] = 0.0f;

            #pragma unroll
            for (int k = 0; k < 4; k++) {
                uint32_t b[8][2];
                #pragma unroll
                for (int q = 0; q < 4; q++) {
                    uint32_t r0, r1, r2, r3;
                    ldsm_x4(r0, r1, r2, r3,
                            b_base + b_lane_off + q * 16 * ROWB + k * 32);
                    b[q * 2 + 0][0] = r0; b[q * 2 + 0][1] = r1;
                    b[q * 2 + 1][0] = r2; b[q * 2 + 1][1] = r3;
                }
                #pragma unroll
                for (int m = 0; m < 2; m++)
                    #pragma unroll
                    for (int nn = 0; nn < 8; nn++)
                        mma_16816(c[m][nn], aF[k][m], b[nn][0], b[nn][1]);
            }

            // ---- Hinge epilogue; classes direct from gmem (L1-resident) ----
            const int* cj = cls + cbj * 128 + wn * 64 + tq * 2;
            float l0 = 0.0f, l1 = 0.0f;
            #pragma unroll
            for (int m = 0; m < 2; m++) {
                const int ci0 = m ? ci10 : ci00;
                const int ci1 = m ? ci11 : ci01;
                #pragma unroll
                for (int nn = 0; nn < 8; nn++) {
                    const int2 cjp = __ldg((const int2*)(cj + nn * 8));
                    float v0 = c[m][nn][0], v1 = c[m][nn][1];
                    float v2 = c[m][nn][2], v3 = c[m][nn][3];
                    l0 += (ci0 == cjp.x) ? (1.0f - v0) : fmaxf(v0 + MC, 0.0f);
                    l1 += (ci0 == cjp.y) ? (1.0f - v1) : fmaxf(v1 + MC, 0.0f);
                    l0 += (ci1 == cjp.x) ? (1.0f - v2) : fmaxf(v2 + MC, 0.0f);
                    l1 += (ci1 == cjp.y) ? (1.0f - v3) : fmaxf(v3 + MC, 0.0f);
                }
            }
            float tl = l0 + l1;
            lsum += (cbi == cbj) ? tl : 2.0f * tl;  // off-diag counted twice
            wcnt++;
        }
    }

    // ---------------- One reduce + atomic per block --------------------------
    #pragma unroll
    for (int o = 16; o; o >>= 1) lsum += __shfl_xor_sync(0xffffffffu, lsum, o);
    if (lane == 0) red[wid] = lsum;
    __syncthreads();
    if (tid == 0) {
        float tt = red[0] + red[1] + red[2] + red[3];
        atomicAdd(&g_accum, (double)tt);
        __threadfence();
        unsigned old = atomicAdd(&g_done_ctr, 1u);
        if (old == (unsigned)(NWORKERS - 1)) {
            double a = atomicAdd(&g_accum, 0.0);
            out[0] = (float)(a / ((double)NROWS * (double)NROWS));
            g_accum     = 0.0;
            g_done_ctr  = 0u;
            g_prep_done = 0u;
            g_work      = 0u;
        }
    }
}

extern "C" void kernel_launch(void* const* d_in, const int* in_sizes, int n_in,
                              void* d_out, int out_size) {
    const float* bottleneck = (const float*)d_in[0];
    const int*   class_map  = (const int*)d_in[1];
    float*       out        = (float*)d_out;

    cudaFuncSetAttribute(fused_kernel,
                         cudaFuncAttributeMaxDynamicSharedMemorySize,
                         SMEM_TOTAL);
    fused_kernel<<<NWORKERS, THREADS, SMEM_TOTAL>>>(bottleneck, class_map, out);
}

// round 16
// speedup vs baseline: 1.2044x; 1.2044x over previous
#include <cuda_runtime.h>
#include <cuda_bf16.h>
#include <math.h>
#include <cstdint>

#define NROWS 8192
#define DDIM  64
#define MARGIN 1.1f
#define EPS 1e-8f
#define TILE 128
#define NPREP 64
#define NWORKERS 296              // 2 CTAs/SM x 148 SMs
#define NUNITS 600                // 296x5 + 296x2 + 8x1 = 2080 tiles
#define ROWB 144
#define BUFB (TILE * ROWB)        // 18432 B
#define SMEM_TOTAL (4 * BUFB + 64)   // A0 A1 B0 B1

// Scratch (no allocs allowed).
__device__ __align__(16) __nv_bfloat16 g_xb[NROWS * DDIM];
__device__ double   g_accum;
__device__ unsigned g_prep_done;
__device__ unsigned g_done_ctr;
__device__ unsigned g_work;

__device__ __forceinline__ uint32_t smem_u32(const void* p) {
    uint32_t a;
    asm("{ .reg .u64 t; cvta.to.shared.u64 t, %1; cvt.u32.u64 %0, t; }"
        : "=r"(a) : "l"(p));
    return a;
}

__device__ __forceinline__ void ldsm_x4(uint32_t& r0, uint32_t& r1,
                                        uint32_t& r2, uint32_t& r3,
                                        uint32_t addr) {
    asm volatile("ldmatrix.sync.aligned.m8n8.x4.shared.b16 {%0,%1,%2,%3}, [%4];"
                 : "=r"(r0), "=r"(r1), "=r"(r2), "=r"(r3) : "r"(addr));
}

__device__ __forceinline__ void mma_16816(float* c, const uint32_t* a,
                                          uint32_t b0, uint32_t b1) {
    asm volatile(
        "mma.sync.aligned.m16n8k16.row.col.f32.bf16.bf16.f32 "
        "{%0,%1,%2,%3}, {%4,%5,%6,%7}, {%8,%9}, {%0,%1,%2,%3};"
        : "+f"(c[0]), "+f"(c[1]), "+f"(c[2]), "+f"(c[3])
        : "r"(a[0]), "r"(a[1]), "r"(a[2]), "r"(a[3]), "r"(b0), "r"(b1));
}

__device__ __forceinline__ void cpa16(uint32_t dst, const void* src) {
    asm volatile("cp.async.cg.shared.global [%0], [%1], 16;"
                 :: "r"(dst), "l"(src) : "memory");
}
#define CPA_COMMIT() asm volatile("cp.async.commit_group;" ::: "memory")
#define CPA_WAIT0()  asm volatile("cp.async.wait_group 0;" ::: "memory")

__device__ __forceinline__ void stage_tile(uint32_t dstb,
                                           const __nv_bfloat16* src, int tid) {
    const char* s = (const char*)src;
    #pragma unroll
    for (int r = 0; r < 4; r++) {
        int idx = tid + r * 256;
        int row = idx >> 3;
        int ch  = idx & 7;
        cpa16(dstb + row * ROWB + ch * 16, s + idx * 16);
    }
}

// Linear triangular tile id -> (bi, bj), bi <= bj.
__device__ __forceinline__ void tile_decode(int t, int& bi, int& bj) {
    int b = (int)((129.0f - sqrtf(16641.0f - 8.0f * (float)t)) * 0.5f);
    while (b * (129 - b) / 2 > t) b--;
    while ((b + 1) * (128 - b) / 2 <= t) b++;
    bi = b;
    bj = b + (t - b * (129 - b) / 2);
}

__device__ __forceinline__ void unit_decode(int u, int& s, int& n) {
    if (u < 296)      { s = u * 5;                n = 5; }
    else if (u < 592) { s = 1480 + (u - 296) * 2; n = 2; }
    else              { s = 2072 + (u - 592);     n = 1; }
}

// ---------------------------------------------------------------------------
// Persistent guided-schedule kernel (R14 base) with:
//  (a) double-buffered A/B FRAGMENTS in the k-loop: ldsm for step k+1 issues
//      while HMMAs of step k execute -> no ldsm->mma scoreboard waits;
//  (b) early steal: the next unit is grabbed and its first tile staged during
//      the LAST tile of the current unit -> no exposed L2 latency at unit
//      boundaries.  One barrier per tile, work identical to R14.
// ---------------------------------------------------------------------------
__global__ __launch_bounds__(256, 2) void fused_kernel(
    const float* __restrict__ x, const int* __restrict__ cls,
    float* __restrict__ out) {

    extern __shared__ __align__(16) char dsm[];
    float* red   = (float*)(dsm + 4 * BUFB);
    int*   sunit = (int*)(red + 8);

    const int bid  = blockIdx.x;
    const int tid  = threadIdx.x;
    const int wid  = tid >> 5;
    const int lane = tid & 31;

    // ---------------- Phase 1: prep (normalize -> bf16), blocks 0..63 ------
    if (bid < NPREP) {
        int t    = bid * 256 + tid;
        int row  = t >> 1;
        int half = t & 1;
        const float4* xr = (const float4*)(x + (size_t)row * DDIM + half * 32);
        float4 v[8];
        #pragma unroll
        for (int i = 0; i < 8; i++) v[i] = xr[i];
        float s = 0.0f;
        #pragma unroll
        for (int i = 0; i < 8; i++)
            s += v[i].x * v[i].x + v[i].y * v[i].y +
                 v[i].z * v[i].z + v[i].w * v[i].w;
        s += __shfl_xor_sync(0xffffffffu, s, 1);
        float inv = 1.0f / fmaxf(sqrtf(s), EPS);
        __nv_bfloat16* dst = g_xb + (size_t)row * DDIM + half * 32;
        #pragma unroll
        for (int i = 0; i < 8; i++) {
            __nv_bfloat162 p0 = {__float2bfloat16(v[i].x * inv),
                                 __float2bfloat16(v[i].y * inv)};
            __nv_bfloat162 p1 = {__float2bfloat16(v[i].z * inv),
                                 __float2bfloat16(v[i].w * inv)};
            *(__nv_bfloat162*)(dst + i * 4)     = p0;
            *(__nv_bfloat162*)(dst + i * 4 + 2) = p1;
        }
        __syncthreads();
        if (tid == 0) { __threadfence(); atomicAdd(&g_prep_done, 1u); }
    }

    // ---------------- Device-wide wait for prep ----------------------------
    if (tid == 0) {
        unsigned v;
        do {
            asm volatile("ld.acquire.gpu.u32 %0, [%1];"
                         : "=r"(v) : "l"(&g_prep_done));
            if (v < (unsigned)NPREP) __nanosleep(64);
        } while (v < (unsigned)NPREP);
    }
    __syncthreads();

    const int wm = wid & 3;
    const int wn = wid >> 2;
    const uint32_t aBufu[2] = { smem_u32(dsm), smem_u32(dsm + BUFB) };
    const uint32_t bBufu[2] = { smem_u32(dsm + 2 * BUFB),
                                smem_u32(dsm + 3 * BUFB) };
    const uint32_t a_lane_off =
        (uint32_t)((wm * 32 + (lane & 15)) * ROWB + ((lane >> 4) << 4));
    const uint32_t b_lane_off =
        (uint32_t)((wn * 64 + (lane & 7) + ((lane >> 4) << 3)) * ROWB +
                   (((lane >> 3) & 1) << 4));
    const float MC = MARGIN - 1.0f;
    const int quad = lane >> 2;
    const int tq   = lane & 3;

    int curAbi = -1;
    int aCur   = 0;
    int wcnt   = 0;
    float lsum = 0.0f;

    // ---------------- Acquire first unit + stage its first tile ------------
    if (tid == 0) *sunit = (int)atomicAdd(&g_work, 1u);
    __syncthreads();
    int u = *sunit;
    bool active = (u < NUNITS);
    int s = 0, n = 0, i = 0, cbi = 0, cbj = 0;
    if (active) {
        unit_decode(u, s, n);
        tile_decode(s, cbi, cbj);
        if (cbi != curAbi)
            stage_tile(aBufu[aCur ^ 1], g_xb + (size_t)cbi * TILE * DDIM, tid);
        stage_tile(bBufu[0], g_xb + (size_t)cbj * TILE * DDIM, tid);
        CPA_COMMIT();
    }

    // ==================== Persistent tile stream ============================
    while (active) {
        const bool last = (i == n - 1);
        if (tid == 0 && last) *sunit = (int)atomicAdd(&g_work, 1u);
        CPA_WAIT0();
        __syncthreads();            // tile data ready + sunit visible
        if (cbi != curAbi) { aCur ^= 1; curAbi = cbi; }

        // ---- determine & stage next tile (possibly from the NEXT unit) ----
        int nbi = -1, nbj = -1;
        bool havenext = false;
        if (!last) {
            tile_decode(s + i + 1, nbi, nbj);
            havenext = true;
        } else {
            int u2 = *sunit;
            if (u2 < NUNITS) {
                unit_decode(u2, s, n);
                i = -1;             // incremented to 0 below
                tile_decode(s, nbi, nbj);
                havenext = true;
            }
        }
        if (havenext) {
            if (nbi != curAbi)
                stage_tile(aBufu[aCur ^ 1],
                           g_xb + (size_t)nbi * TILE * DDIM, tid);
            stage_tile(bBufu[(wcnt + 1) & 1],
                       g_xb + (size_t)nbj * TILE * DDIM, tid);
            CPA_COMMIT();
        }

        // ---- row classes for this tile (L1-resident) ----
        const int* cr = cls + cbi * TILE + wm * 32 + quad;
        const int ci00 = __ldg(cr);      const int ci01 = __ldg(cr + 8);
        const int ci10 = __ldg(cr + 16); const int ci11 = __ldg(cr + 24);

        // ---- compute current tile: pipelined fragments ----
        const uint32_t a_base = aBufu[aCur] + a_lane_off;
        const uint32_t b_base = bBufu[wcnt & 1] + b_lane_off;

        uint32_t aR[2][2][4];
        uint32_t bR[2][8][2];
        #pragma unroll
        for (int m = 0; m < 2; m++)
            ldsm_x4(aR[0][m][0], aR[0][m][1], aR[0][m][2], aR[0][m][3],
                    a_base + m * 16 * ROWB);
        #pragma unroll
        for (int q = 0; q < 4; q++) {
            uint32_t r0, r1, r2, r3;
            ldsm_x4(r0, r1, r2, r3, b_base + q * 16 * ROWB);
            bR[0][q * 2 + 0][0] = r0; bR[0][q * 2 + 0][1] = r1;
            bR[0][q * 2 + 1][0] = r2; bR[0][q * 2 + 1][1] = r3;
        }

        float c[2][8][4];
        #pragma unroll
        for (int m = 0; m < 2; m++)
            #pragma unroll
            for (int nn = 0; nn < 8; nn++)
                #pragma unroll
                for (int e = 0; e < 4; e++) c[m][nn][e] = 0.0f;

        #pragma unroll
        for (int k = 0; k < 4; k++) {
            const int cur = k & 1, nxt = cur ^ 1;
            if (k < 3) {            // prefetch fragments for step k+1
                #pragma unroll
                for (int m = 0; m < 2; m++)
                    ldsm_x4(aR[nxt][m][0], aR[nxt][m][1],
                            aR[nxt][m][2], aR[nxt][m][3],
                            a_base + m * 16 * ROWB + (k + 1) * 32);
                #pragma unroll
                for (int q = 0; q < 4; q++) {
                    uint32_t r0, r1, r2, r3;
                    ldsm_x4(r0, r1, r2, r3,
                            b_base + q * 16 * ROWB + (k + 1) * 32);
                    bR[nxt][q * 2 + 0][0] = r0; bR[nxt][q * 2 + 0][1] = r1;
                    bR[nxt][q * 2 + 1][0] = r2; bR[nxt][q * 2 + 1][1] = r3;
                }
            }
            #pragma unroll
            for (int m = 0; m < 2; m++)
                #pragma unroll
                for (int nn = 0; nn < 8; nn++)
                    mma_16816(c[m][nn], aR[cur][m],
                              bR[cur][nn][0], bR[cur][nn][1]);
        }

        // ---- Hinge epilogue ----
        const int* cj = cls + cbj * TILE + wn * 64 + tq * 2;
        float l0 = 0.0f, l1 = 0.0f;
        #pragma unroll
        for (int m = 0; m < 2; m++) {
            const int ci0 = m ? ci10 : ci00;
            const int ci1 = m ? ci11 : ci01;
            #pragma unroll
            for (int nn = 0; nn < 8; nn++) {
                const int2 cjp = __ldg((const int2*)(cj + nn * 8));
                float v0 = c[m][nn][0], v1 = c[m][nn][1];
                float v2 = c[m][nn][2], v3 = c[m][nn][3];
                l0 += (ci0 == cjp.x) ? (1.0f - v0) : fmaxf(v0 + MC, 0.0f);
                l1 += (ci0 == cjp.y) ? (1.0f - v1) : fmaxf(v1 + MC, 0.0f);
                l0 += (ci1 == cjp.x) ? (1.0f - v2) : fmaxf(v2 + MC, 0.0f);
                l1 += (ci1 == cjp.y) ? (1.0f - v3) : fmaxf(v3 + MC, 0.0f);
            }
        }
        float tl = l0 + l1;
        lsum += (cbi == cbj) ? tl : 2.0f * tl;

        wcnt++;
        if (!havenext) break;
        cbi = nbi; cbj = nbj; i++;
    }

    // ---------------- One reduce + atomic per block --------------------------
    #pragma unroll
    for (int o = 16; o; o >>= 1) lsum += __shfl_xor_sync(0xffffffffu, lsum, o);
    if (lane == 0) red[wid] = lsum;
    __syncthreads();
    if (tid == 0) {
        float tt = 0.0f;
        #pragma unroll
        for (int w = 0; w < 8; w++) tt += red[w];
        atomicAdd(&g_accum, (double)tt);
        __threadfence();
        unsigned old = atomicAdd(&g_done_ctr, 1u);
        if (old == (unsigned)(NWORKERS - 1)) {
            double a = atomicAdd(&g_accum, 0.0);
            out[0] = (float)(a / ((double)NROWS * (double)NROWS));
            g_accum     = 0.0;
            g_done_ctr  = 0u;
            g_prep_done = 0u;
            g_work      = 0u;
        }
    }
}

extern "C" void kernel_launch(void* const* d_in, const int* in_sizes, int n_in,
                              void* d_out, int out_size) {
    const float* bottleneck = (const float*)d_in[0];
    const int*   class_map  = (const int*)d_in[1];
    float*       out        = (float*)d_out;

    cudaFuncSetAttribute(fused_kernel,
                         cudaFuncAttributeMaxDynamicSharedMemorySize,
                         SMEM_TOTAL);
    fused_kernel<<<NWORKERS, 256, SMEM_TOTAL>>>(bottleneck, class_map, out);
}